// round 2
// baseline (speedup 1.0000x reference)
#include <cuda_runtime.h>
#include <cuda_fp16.h>
#include <math.h>

// Problem constants (fixed by dataset)
#define NN 20000
#define EE 100000
#define CC 32
#define NHEAD 4
#define DH 8
#define NB 16
#define HID 64

// ---------------------------------------------------------------------------
// Static scratch (no allocation allowed)
// ---------------------------------------------------------------------------
__device__ float  g_q[NN * CC];          // query, scaled 1/sqrt(C)
__device__ float  g_Pbk[NN * CC];        // b2 bias term, K path (scaled tp_norm)
__device__ float  g_Pbv[NN * CC];        // b2 bias term, V path
__device__ __half g_Pk16[(size_t)NN * 2048]; // P[n][k*64+h], K path, fp16, scaled
__device__ __half g_Pv16[(size_t)NN * 2048]; // P, V path
__device__ float  g_W2t[2][32 * 2048];   // transposed+scaled w2: [i][k*64+h]
__device__ float  g_den[NN * NHEAD];
__device__ float  g_num[NN * CC];
__device__ int    g_cnt[NN];             // out-degree histogram / scan scratch
__device__ int    g_ofs[NN];             // scatter cursors
__device__ int    g_eorder[EE];          // edge ids sorted by src

#define INV_SQRT_C 0.17677669529663687f  /* 1/sqrt(32) */
#define DOT_SCALE  0.04419417382415922f  /* (1/8) * (1/sqrt(8)) */

__device__ __forceinline__ float decode_scalar(const int* p) {
    int iv = *p;
    if (iv > -(1 << 23) && iv < (1 << 23)) return (float)iv;
    return __int_as_float(iv);
}

// packed f32x2 helpers (Blackwell FFMA2 path)
__device__ __forceinline__ unsigned long long pack2(float x, float y) {
    unsigned long long r;
    asm("mov.b64 %0, {%1,%2};" : "=l"(r) : "f"(x), "f"(y));
    return r;
}
__device__ __forceinline__ float2 unpack2(unsigned long long v) {
    float2 r;
    asm("mov.b64 {%0,%1}, %2;" : "=f"(r.x), "=f"(r.y) : "l"(v));
    return r;
}
__device__ __forceinline__ void ffma2(unsigned long long& d,
                                      unsigned long long a,
                                      unsigned long long b) {
    asm("fma.rn.f32x2 %0, %1, %2, %0;" : "+l"(d) : "l"(a), "l"(b));
}

// ---------------------------------------------------------------------------
// K0: zero accumulators + histogram (every replay)
// ---------------------------------------------------------------------------
__global__ void k0_init(int n) {
    int i = blockIdx.x * blockDim.x + threadIdx.x;
    int a = n * CC, b = a + n * NHEAD, c = b + n;
    if (i < a) g_num[i] = 0.f;
    else if (i < b) g_den[i - a] = 0.f;
    else if (i < c) g_cnt[i - b] = 0;
}

// ---------------------------------------------------------------------------
// KT: transpose w2 into [i][k*64+h] layout, fold in tp_norm
// ---------------------------------------------------------------------------
__global__ void kt_transpose(const float* __restrict__ w2k,
                             const float* __restrict__ w2v) {
    int o = blockIdx.x * blockDim.x + threadIdx.x;   // 2*65536 total
    if (o >= 2 * 65536) return;
    int p = o >> 16;
    int q = o & 65535;
    int i = q >> 11;          // input channel 0..31
    int r = q & 2047;
    int k = r >> 6;           // output channel 0..31
    int h = r & 63;           // hidden unit 0..63
    const float* W = p ? w2v : w2k;
    g_W2t[p][q] = W[h * 1024 + i * 32 + k] * INV_SQRT_C;
}

// ---------------------------------------------------------------------------
// CSR build: histogram -> scan -> scatter
// ---------------------------------------------------------------------------
__global__ void kh_hist(const int* __restrict__ ei, int e) {
    int i = blockIdx.x * blockDim.x + threadIdx.x;
    if (i < e) atomicAdd(&g_cnt[ei[i]], 1);
}

__global__ void ks_scan(int n) {   // single block, 1024 threads
    __shared__ int part[1024];
    int t = threadIdx.x;
    int chunk = (n + 1023) >> 10;
    int beg = t * chunk;
    int end = min(beg + chunk, n);
    int s = 0;
    for (int i = beg; i < end; i++) s += g_cnt[i];
    part[t] = s;
    __syncthreads();
    for (int off = 1; off < 1024; off <<= 1) {
        int v = part[t] + ((t >= off) ? part[t - off] : 0);
        __syncthreads();
        part[t] = v;
        __syncthreads();
    }
    int excl = (t == 0) ? 0 : part[t - 1];
    for (int i = beg; i < end; i++) {
        g_ofs[i] = excl;
        excl += g_cnt[i];
    }
}

__global__ void kc_scatter(const int* __restrict__ ei, int e) {
    int i = blockIdx.x * blockDim.x + threadIdx.x;
    if (i < e) {
        int pos = atomicAdd(&g_ofs[ei[i]], 1);
        g_eorder[pos] = i;
    }
}

// ---------------------------------------------------------------------------
// K1: per-node q projection + b2 bias terms
// ---------------------------------------------------------------------------
__global__ void k1_node_pre(const float* __restrict__ nf,
                            const float* __restrict__ w_q,
                            const float* __restrict__ b2k,
                            const float* __restrict__ b2v, int n) {
    __shared__ float s_wq[1024], s_bk[1024], s_bv[1024];
    for (int i = threadIdx.x; i < 1024; i += blockDim.x) {
        s_wq[i] = w_q[i];
        s_bk[i] = b2k[i];
        s_bv[i] = b2v[i];
    }
    __syncthreads();
    int warp = threadIdx.x >> 5;
    int lane = threadIdx.x & 31;
    int node = blockIdx.x * (blockDim.x >> 5) + warp;
    if (node >= n) return;
    float fv = nf[node * 32 + lane];
    float q = 0.f, bk = 0.f, bv = 0.f;
#pragma unroll
    for (int i = 0; i < 32; i++) {
        float a = __shfl_sync(0xffffffffu, fv, i);
        q  = fmaf(a, s_wq[i * 32 + lane], q);
        bk = fmaf(a, s_bk[i * 32 + lane], bk);
        bv = fmaf(a, s_bv[i * 32 + lane], bv);
    }
    g_q[node * 32 + lane]   = q  * INV_SQRT_C;
    g_Pbk[node * 32 + lane] = bk * INV_SQRT_C;
    g_Pbv[node * 32 + lane] = bv * INV_SQRT_C;
}

// ---------------------------------------------------------------------------
// K2: P GEMM, (n x 32) @ (32 x 2048) with FFMA2, fp16 output.
// Tile 128 nodes x 128 cols, K=32.  grid.z = path.
// ---------------------------------------------------------------------------
__global__ void __launch_bounds__(256) k2_pgemm(const float* __restrict__ nf, int n) {
    __shared__ float As[32][132];
    __shared__ float Bs[32][132];
    int path = blockIdx.z;
    const float* W = g_W2t[path];
    __half* P = path ? g_Pv16 : g_Pk16;
    int n0 = blockIdx.x * 128;
    int j0 = blockIdx.y * 128;
    int tid = threadIdx.x;

    // A tile (transposed into smem): 128 nodes x 32 k
#pragma unroll
    for (int p = 0; p < 4; p++) {
        int f4 = p * 256 + tid;          // 1024 float4
        int node = f4 >> 3;
        int k4 = (f4 & 7) << 2;
        float4 v = make_float4(0.f, 0.f, 0.f, 0.f);
        if (n0 + node < n) v = *(const float4*)(nf + (size_t)(n0 + node) * 32 + k4);
        As[k4 + 0][node] = v.x;
        As[k4 + 1][node] = v.y;
        As[k4 + 2][node] = v.z;
        As[k4 + 3][node] = v.w;
    }
    // B tile: coalesced from transposed W2t
#pragma unroll
    for (int p = 0; p < 4; p++) {
        int f4 = p * 256 + tid;          // 1024 float4 = 4096 floats
        int i = f4 >> 5;                 // row 0..31
        int jj = (f4 & 31) << 2;         // col within tile
        float4 v = *(const float4*)(W + i * 2048 + j0 + jj);
        *(float4*)(&Bs[i][jj]) = v;
    }
    __syncthreads();

    int tr = tid >> 4, tc = tid & 15;
    unsigned long long acc[8][4];
#pragma unroll
    for (int r = 0; r < 8; r++)
#pragma unroll
        for (int c = 0; c < 4; c++) acc[r][c] = 0ull;

#pragma unroll
    for (int k = 0; k < 32; k++) {
        float a[8];
        *(float4*)(a)     = *(float4*)(&As[k][tr * 8]);
        *(float4*)(a + 4) = *(float4*)(&As[k][tr * 8 + 4]);
        unsigned long long bb[4];
#pragma unroll
        for (int c = 0; c < 4; c++)
            bb[c] = *(const unsigned long long*)(&Bs[k][tc * 8 + 2 * c]);
#pragma unroll
        for (int r = 0; r < 8; r++) {
            unsigned long long aa = pack2(a[r], a[r]);
#pragma unroll
            for (int c = 0; c < 4; c++) ffma2(acc[r][c], aa, bb[c]);
        }
    }

#pragma unroll
    for (int r = 0; r < 8; r++) {
        int node = n0 + tr * 8 + r;
        if (node < n) {
            __half* dst = P + (size_t)node * 2048 + j0 + tc * 8;
            unsigned int o[4];
#pragma unroll
            for (int c = 0; c < 4; c++) {
                float2 f = unpack2(acc[r][c]);
                __half2 hh = __floats2half2_rn(f.x, f.y);
                o[c] = *(unsigned int*)&hh;
            }
            *(uint4*)dst = make_uint4(o[0], o[1], o[2], o[3]);
        }
    }
}

// ---------------------------------------------------------------------------
// K3: fused edge pass, src-sorted order for P locality. One warp per edge.
// ---------------------------------------------------------------------------
__global__ void __launch_bounds__(256) k3_edge(
    const int* __restrict__ ei, const float* __restrict__ esh,
    const float* __restrict__ remb, const float* __restrict__ elen,
    const float* __restrict__ w1k, const float* __restrict__ b1k,
    const float* __restrict__ w1v, const float* __restrict__ b1v,
    const float* __restrict__ wdot, const int* __restrict__ maxr_p,
    int e_count) {
    __shared__ float s_w1k[NB * HID], s_w1v[NB * HID];
    __shared__ float s_b1k[HID], s_b1v[HID];
    __shared__ float s_wdot[DH * DH];
    __shared__ float s_h[8][128];        // per-warp hidden: [pathK 0..63][pathV 64..127]
    for (int i = threadIdx.x; i < NB * HID; i += blockDim.x) {
        s_w1k[i] = w1k[i];
        s_w1v[i] = w1v[i];
    }
    if (threadIdx.x < HID) {
        s_b1k[threadIdx.x] = b1k[threadIdx.x];
        s_b1v[threadIdx.x] = b1v[threadIdx.x];
    }
    if (threadIdx.x < DH * DH) s_wdot[threadIdx.x] = wdot[threadIdx.x];
    __syncthreads();

    int warp = threadIdx.x >> 5;
    int lane = threadIdx.x & 31;
    int widx = blockIdx.x * (blockDim.x >> 5) + warp;
    if (widx >= e_count) return;
    int e = g_eorder[widx];

    int src = ei[e];
    int dst = ei[e_count + e];
    float shv = esh[e];

    // radial MLP layer 1 + SiLU (lane owns hidden units lane, lane+32)
    float rv = (lane < NB) ? remb[(size_t)e * NB + lane] : 0.f;
    float zk0 = s_b1k[lane], zk1 = s_b1k[lane + 32];
    float zv0 = s_b1v[lane], zv1 = s_b1v[lane + 32];
#pragma unroll
    for (int r = 0; r < NB; r++) {
        float x = __shfl_sync(0xffffffffu, rv, r);
        zk0 = fmaf(x, s_w1k[r * HID + lane], zk0);
        zk1 = fmaf(x, s_w1k[r * HID + lane + 32], zk1);
        zv0 = fmaf(x, s_w1v[r * HID + lane], zv0);
        zv1 = fmaf(x, s_w1v[r * HID + lane + 32], zv1);
    }
    s_h[warp][lane]       = zk0 / (1.f + expf(-zk0));
    s_h[warp][lane + 32]  = zk1 / (1.f + expf(-zk1));
    s_h[warp][lane + 64]  = zv0 / (1.f + expf(-zv0));
    s_h[warp][lane + 96]  = zv1 / (1.f + expf(-zv1));
    __syncwarp();

    // contract hidden with fp16 P rows: lane = output channel k
    const uint4* pk4 = (const uint4*)(g_Pk16 + (size_t)src * 2048 + lane * 64);
    const uint4* pv4 = (const uint4*)(g_Pv16 + (size_t)src * 2048 + lane * 64);
    float akx = 0.f, aky = 0.f, avx = 0.f, avy = 0.f;
#pragma unroll
    for (int c = 0; c < 8; c++) {
        uint4 vk = pk4[c];
        uint4 vv = pv4[c];
        const __half2* hk = (const __half2*)&vk;
        const __half2* hv = (const __half2*)&vv;
#pragma unroll
        for (int t = 0; t < 4; t++) {
            int h = c * 8 + t * 2;
            float2 hidk = *(const float2*)&s_h[warp][h];
            float2 hidv = *(const float2*)&s_h[warp][64 + h];
            float2 pk = __half22float2(hk[t]);
            float2 pv = __half22float2(hv[t]);
            akx = fmaf(hidk.x, pk.x, akx);
            aky = fmaf(hidk.y, pk.y, aky);
            avx = fmaf(hidv.x, pv.x, avx);
            avy = fmaf(hidv.y, pv.y, avy);
        }
    }
    float k_e = shv * (akx + aky + g_Pbk[dst * 0 + src * 32 + lane]);
    float v_e = shv * (avx + avy + g_Pbv[src * 32 + lane]);

    // per-head bilinear logit
    int head = lane >> 3;
    int j = lane & 7;
    float qv = g_q[dst * 32 + lane];
    float cj = 0.f;
#pragma unroll
    for (int i = 0; i < DH; i++) {
        float qi = __shfl_sync(0xffffffffu, qv, head * 8 + i);
        cj = fmaf(qi, s_wdot[i * 8 + j], cj);
    }
    float prod = cj * k_e;
    prod += __shfl_xor_sync(0xffffffffu, prod, 1);
    prod += __shfl_xor_sync(0xffffffffu, prod, 2);
    prod += __shfl_xor_sync(0xffffffffu, prod, 4);

    float max_r = decode_scalar(maxr_p);
    float L = elen[e];
    float cut = 1.f / (1.f + expf(-10.f * (1.f - L / max_r)));
    float logit = prod * DOT_SCALE * cut;
    float ex = expf(logit);      // |logit| << 1 by construction; no max-shift

    if (j == 0) atomicAdd(&g_den[dst * NHEAD + head], ex);
    atomicAdd(&g_num[dst * 32 + lane], ex * v_e);
}

// ---------------------------------------------------------------------------
// K5: per-node epilogue (unchanged)
// ---------------------------------------------------------------------------
__global__ void k5_final(const float* __restrict__ nf,
                         const float* __restrict__ w_out,
                         const float* __restrict__ ffn_w1,
                         const float* __restrict__ ffn_w2,
                         float* __restrict__ out, int n) {
    __shared__ float s_wo[1024], s_f1[2048], s_f2[2048];
    for (int i = threadIdx.x; i < 1024; i += blockDim.x) s_wo[i] = w_out[i];
    for (int i = threadIdx.x; i < 2048; i += blockDim.x) {
        s_f1[i] = ffn_w1[i];
        s_f2[i] = ffn_w2[i];
    }
    __syncthreads();
    int warp = threadIdx.x >> 5;
    int lane = threadIdx.x & 31;
    int node = blockIdx.x * (blockDim.x >> 5) + warp;
    if (node >= n) return;

    float numv = g_num[node * 32 + lane];
    float den = g_den[node * NHEAD + (lane >> 3)];
    float agg = (den > 0.f) ? numv / den : 0.f;

    float o = 0.f;
#pragma unroll
    for (int i = 0; i < 32; i++) {
        float a = __shfl_sync(0xffffffffu, agg, i);
        o = fmaf(a, s_wo[i * 32 + lane], o);
    }
    float attn = nf[node * 32 + lane] + o * INV_SQRT_C;

    float h0 = 0.f, h1 = 0.f;
#pragma unroll
    for (int i = 0; i < 32; i++) {
        float a = __shfl_sync(0xffffffffu, attn, i);
        h0 = fmaf(a, s_f1[i * 64 + lane], h0);
        h1 = fmaf(a, s_f1[i * 64 + lane + 32], h1);
    }
    h0 *= INV_SQRT_C;
    h1 *= INV_SQRT_C;
    float g0 = h0 / (1.f + expf(-fabsf(h0)));
    float g1 = h1 / (1.f + expf(-fabsf(h1)));

    float f = 0.f;
#pragma unroll
    for (int jj = 0; jj < 64; jj++) {
        float g = __shfl_sync(0xffffffffu, (jj < 32) ? g0 : g1, jj & 31);
        f = fmaf(g, s_f2[jj * 32 + lane], f);
    }
    out[node * 32 + lane] = attn + f * 0.125f;
}

// ---------------------------------------------------------------------------
extern "C" void kernel_launch(void* const* d_in, const int* in_sizes, int n_in,
                              void* d_out, int out_size) {
    const float* nf     = (const float*)d_in[0];
    const int*   ei     = (const int*)d_in[1];
    const float* esh    = (const float*)d_in[2];
    const float* remb   = (const float*)d_in[3];
    const float* elen   = (const float*)d_in[4];
    const int*   maxr   = (const int*)d_in[5];
    const float* w_q    = (const float*)d_in[6];
    const float* fck_w1 = (const float*)d_in[7];
    const float* fck_b1 = (const float*)d_in[8];
    const float* fck_w2 = (const float*)d_in[9];
    const float* fck_b2 = (const float*)d_in[10];
    const float* fcv_w1 = (const float*)d_in[11];
    const float* fcv_b1 = (const float*)d_in[12];
    const float* fcv_w2 = (const float*)d_in[13];
    const float* fcv_b2 = (const float*)d_in[14];
    const float* w_dot  = (const float*)d_in[15];
    const float* w_out  = (const float*)d_in[16];
    const float* ffn_w1 = (const float*)d_in[17];
    const float* ffn_w2 = (const float*)d_in[18];

    int n = in_sizes[0] / CC;
    int e = in_sizes[1] / 2;

    int tot0 = n * (CC + NHEAD + 1);
    k0_init<<<(tot0 + 255) / 256, 256>>>(n);
    kt_transpose<<<(2 * 65536 + 255) / 256, 256>>>(fck_w2, fcv_w2);
    kh_hist<<<(e + 255) / 256, 256>>>(ei, e);
    ks_scan<<<1, 1024>>>(n);
    kc_scatter<<<(e + 255) / 256, 256>>>(ei, e);
    k1_node_pre<<<(n + 7) / 8, 256>>>(nf, w_q, fck_b2, fcv_b2, n);
    dim3 g2((n + 127) / 128, 16, 2);
    k2_pgemm<<<g2, 256>>>(nf, n);
    k3_edge<<<(e + 7) / 8, 256>>>(ei, esh, remb, elen, fck_w1, fck_b1,
                                  fcv_w1, fcv_b1, w_dot, maxr, e);
    k5_final<<<(n + 7) / 8, 256>>>(nf, w_out, ffn_w1, ffn_w2, (float*)d_out, n);
}

// round 5
// speedup vs baseline: 1.4785x; 1.4785x over previous
#include <cuda_runtime.h>
#include <cuda_fp16.h>
#include <math.h>

// Problem constants (fixed by dataset)
#define NN 20000
#define EE 100000
#define CC 32
#define NHEAD 4
#define DH 8
#define NB 16
#define HID 64

// ---------------------------------------------------------------------------
// Static scratch (no allocation allowed)
// ---------------------------------------------------------------------------
__device__ float  g_q[NN * CC];
__device__ float  g_Pbk[NN * CC];
__device__ float  g_Pbv[NN * CC];
// P layout: [n][hb][k][t], index = n*2048 + hb*256 + k*8 + t, h = hb*8+t
__device__ __half g_Pk16[(size_t)NN * 2048];
__device__ __half g_Pv16[(size_t)NN * 2048];
__device__ float  g_W2t[2][32 * 2048];   // [i][j] with j in the P layout above
__device__ float  g_den[NN * NHEAD];
__device__ float  g_num[NN * CC];
__device__ int    g_cnt[NN];
__device__ int    g_ofs[NN];
__device__ int    g_blk[32];             // per-block sums for scan
__device__ int    g_eorder[EE];

#define INV_SQRT_C 0.17677669529663687f  /* 1/sqrt(32) */
#define DOT_SCALE  0.04419417382415922f  /* (1/8) * (1/sqrt(8)) */
#define SCAN_BLK 20                       /* ceil(20000/1024) */

__device__ __forceinline__ float decode_scalar(const int* p) {
    int iv = *p;
    if (iv > -(1 << 23) && iv < (1 << 23)) return (float)iv;
    return __int_as_float(iv);
}

// packed f32x2 helpers (Blackwell FFMA2 path)
__device__ __forceinline__ unsigned long long pack2(float x, float y) {
    unsigned long long r;
    asm("mov.b64 %0, {%1,%2};" : "=l"(r) : "f"(x), "f"(y));
    return r;
}
__device__ __forceinline__ float2 unpack2(unsigned long long v) {
    float2 r;
    asm("mov.b64 {%0,%1}, %2;" : "=f"(r.x), "=f"(r.y) : "l"(v));
    return r;
}
__device__ __forceinline__ void ffma2(unsigned long long& d,
                                      unsigned long long a,
                                      unsigned long long b) {
    asm("fma.rn.f32x2 %0, %1, %2, %0;" : "+l"(d) : "l"(a), "l"(b));
}

// ---------------------------------------------------------------------------
// K0: zero accumulators + histogram (every replay)
// ---------------------------------------------------------------------------
__global__ void k0_init(int n) {
    int i = blockIdx.x * blockDim.x + threadIdx.x;
    int a = n * CC, b = a + n * NHEAD, c = b + n;
    if (i < a) g_num[i] = 0.f;
    else if (i < b) g_den[i - a] = 0.f;
    else if (i < c) g_cnt[i - b] = 0;
}

// ---------------------------------------------------------------------------
// KT: transpose w2 into [i][hb*256 + k*8 + t], fold in tp_norm
// ---------------------------------------------------------------------------
__global__ void kt_transpose(const float* __restrict__ w2k,
                             const float* __restrict__ w2v) {
    int o = blockIdx.x * blockDim.x + threadIdx.x;   // 2*65536 total
    if (o >= 2 * 65536) return;
    int p = o >> 16;
    int q = o & 65535;
    int i = q >> 11;           // input channel 0..31
    int j = q & 2047;
    int hb = j >> 8;
    int rem = j & 255;
    int k = rem >> 3;          // output channel 0..31
    int t = rem & 7;
    int h = hb * 8 + t;        // hidden unit 0..63
    const float* W = p ? w2v : w2k;
    g_W2t[p][q] = W[h * 1024 + i * 32 + k] * INV_SQRT_C;
}

// ---------------------------------------------------------------------------
// CSR build: histogram -> 3-phase multi-block exclusive scan -> scatter
// ---------------------------------------------------------------------------
__global__ void kh_hist(const int* __restrict__ ei, int e) {
    int i = blockIdx.x * blockDim.x + threadIdx.x;
    if (i < e) atomicAdd(&g_cnt[ei[i]], 1);
}

__global__ void ksA_blocksum(int n) {   // SCAN_BLK blocks x 1024
    __shared__ int ws[32];
    int t = threadIdx.x;
    int i = blockIdx.x * 1024 + t;
    int v = (i < n) ? g_cnt[i] : 0;
    int s = v;
#pragma unroll
    for (int off = 1; off < 32; off <<= 1) s += __shfl_xor_sync(0xffffffffu, s, off);
    if ((t & 31) == 0) ws[t >> 5] = s;
    __syncthreads();
    if (t < 32) {
        int x = ws[t];
#pragma unroll
        for (int off = 1; off < 32; off <<= 1) x += __shfl_xor_sync(0xffffffffu, x, off);
        if (t == 0) g_blk[blockIdx.x] = x;
    }
}

__global__ void ksB_scanblk() {         // 1 warp: exclusive scan of SCAN_BLK sums
    int t = threadIdx.x;
    int v = (t < SCAN_BLK) ? g_blk[t] : 0;
    int s = v;
#pragma unroll
    for (int off = 1; off < 32; off <<= 1) {
        int u = __shfl_up_sync(0xffffffffu, s, off);
        if (t >= off) s += u;
    }
    if (t < SCAN_BLK) g_blk[t] = s - v;  // exclusive
}

__global__ void ksC_scan(int n) {       // SCAN_BLK blocks x 1024: local scan + offset
    __shared__ int ws[32];
    int t = threadIdx.x;
    int warp = t >> 5, lane = t & 31;
    int i = blockIdx.x * 1024 + t;
    int v = (i < n) ? g_cnt[i] : 0;
    int s = v;
#pragma unroll
    for (int off = 1; off < 32; off <<= 1) {
        int u = __shfl_up_sync(0xffffffffu, s, off);
        if (lane >= off) s += u;
    }
    if (lane == 31) ws[warp] = s;
    __syncthreads();
    if (t < 32) {
        int x = ws[t];
#pragma unroll
        for (int off = 1; off < 32; off <<= 1) {
            int u = __shfl_up_sync(0xffffffffu, x, off);
            if (t >= off) x += u;
        }
        ws[t] = x;
    }
    __syncthreads();
    int base = g_blk[blockIdx.x] + (warp > 0 ? ws[warp - 1] : 0);
    if (i < n) g_ofs[i] = base + s - v;   // exclusive prefix
}

__global__ void kc_scatter(const int* __restrict__ ei, int e) {
    int i = blockIdx.x * blockDim.x + threadIdx.x;
    if (i < e) {
        int pos = atomicAdd(&g_ofs[ei[i]], 1);
        g_eorder[pos] = i;
    }
}

// ---------------------------------------------------------------------------
// K1: per-node q projection + b2 bias terms
// ---------------------------------------------------------------------------
__global__ void k1_node_pre(const float* __restrict__ nf,
                            const float* __restrict__ w_q,
                            const float* __restrict__ b2k,
                            const float* __restrict__ b2v, int n) {
    __shared__ float s_wq[1024], s_bk[1024], s_bv[1024];
    for (int i = threadIdx.x; i < 1024; i += blockDim.x) {
        s_wq[i] = w_q[i];
        s_bk[i] = b2k[i];
        s_bv[i] = b2v[i];
    }
    __syncthreads();
    int warp = threadIdx.x >> 5;
    int lane = threadIdx.x & 31;
    int node = blockIdx.x * (blockDim.x >> 5) + warp;
    if (node >= n) return;
    float fv = nf[node * 32 + lane];
    float q = 0.f, bk = 0.f, bv = 0.f;
#pragma unroll
    for (int i = 0; i < 32; i++) {
        float a = __shfl_sync(0xffffffffu, fv, i);
        q  = fmaf(a, s_wq[i * 32 + lane], q);
        bk = fmaf(a, s_bk[i * 32 + lane], bk);
        bv = fmaf(a, s_bv[i * 32 + lane], bv);
    }
    g_q[node * 32 + lane]   = q  * INV_SQRT_C;
    g_Pbk[node * 32 + lane] = bk * INV_SQRT_C;
    g_Pbv[node * 32 + lane] = bv * INV_SQRT_C;
}

// ---------------------------------------------------------------------------
// K2: P GEMM, (n x 32) @ (32 x 2048) with FFMA2, fp16 output.
// ---------------------------------------------------------------------------
__global__ void __launch_bounds__(256) k2_pgemm(const float* __restrict__ nf, int n) {
    __shared__ float As[32][132];
    __shared__ float Bs[32][132];
    int path = blockIdx.z;
    const float* W = g_W2t[path];
    __half* P = path ? g_Pv16 : g_Pk16;
    int n0 = blockIdx.x * 128;
    int j0 = blockIdx.y * 128;
    int tid = threadIdx.x;

#pragma unroll
    for (int p = 0; p < 4; p++) {
        int f4 = p * 256 + tid;
        int node = f4 >> 3;
        int k4 = (f4 & 7) << 2;
        float4 v = make_float4(0.f, 0.f, 0.f, 0.f);
        if (n0 + node < n) v = *(const float4*)(nf + (size_t)(n0 + node) * 32 + k4);
        As[k4 + 0][node] = v.x;
        As[k4 + 1][node] = v.y;
        As[k4 + 2][node] = v.z;
        As[k4 + 3][node] = v.w;
    }
#pragma unroll
    for (int p = 0; p < 4; p++) {
        int f4 = p * 256 + tid;
        int i = f4 >> 5;
        int jj = (f4 & 31) << 2;
        float4 v = *(const float4*)(W + i * 2048 + j0 + jj);
        *(float4*)(&Bs[i][jj]) = v;
    }
    __syncthreads();

    int tr = tid >> 4, tc = tid & 15;
    unsigned long long acc[8][4];
#pragma unroll
    for (int r = 0; r < 8; r++)
#pragma unroll
        for (int c = 0; c < 4; c++) acc[r][c] = 0ull;

#pragma unroll
    for (int k = 0; k < 32; k++) {
        float a[8];
        *(float4*)(a)     = *(float4*)(&As[k][tr * 8]);
        *(float4*)(a + 4) = *(float4*)(&As[k][tr * 8 + 4]);
        unsigned long long bb[4];
#pragma unroll
        for (int c = 0; c < 4; c++)
            bb[c] = *(const unsigned long long*)(&Bs[k][tc * 8 + 2 * c]);
#pragma unroll
        for (int r = 0; r < 8; r++) {
            unsigned long long aa = pack2(a[r], a[r]);
#pragma unroll
            for (int c = 0; c < 4; c++) ffma2(acc[r][c], aa, bb[c]);
        }
    }

#pragma unroll
    for (int r = 0; r < 8; r++) {
        int node = n0 + tr * 8 + r;
        if (node < n) {
            __half* dst = P + (size_t)node * 2048 + j0 + tc * 8;
            unsigned int o[4];
#pragma unroll
            for (int c = 0; c < 4; c++) {
                float2 f = unpack2(acc[r][c]);
                __half2 hh = __floats2half2_rn(f.x, f.y);
                o[c] = *(unsigned int*)&hh;
            }
            *(uint4*)dst = make_uint4(o[0], o[1], o[2], o[3]);
        }
    }
}

// ---------------------------------------------------------------------------
// K3: fused edge pass, src-sorted, coalesced interleaved-fp16 P gather.
// One warp per edge; lane = channel k.
// ---------------------------------------------------------------------------
__global__ void __launch_bounds__(256) k3_edge(
    const int* __restrict__ ei, const float* __restrict__ esh,
    const float* __restrict__ remb, const float* __restrict__ elen,
    const float* __restrict__ w1k, const float* __restrict__ b1k,
    const float* __restrict__ w1v, const float* __restrict__ b1v,
    const float* __restrict__ wdot, const int* __restrict__ maxr_p,
    int e_count) {
    __shared__ float s_w1k[NB * HID], s_w1v[NB * HID];
    __shared__ float s_b1k[HID], s_b1v[HID];
    __shared__ float s_wdot[DH * DH];
    __shared__ float s_h[8][128];        // per-warp hidden: [K 0..63][V 64..127]
    for (int i = threadIdx.x; i < NB * HID; i += blockDim.x) {
        s_w1k[i] = w1k[i];
        s_w1v[i] = w1v[i];
    }
    if (threadIdx.x < HID) {
        s_b1k[threadIdx.x] = b1k[threadIdx.x];
        s_b1v[threadIdx.x] = b1v[threadIdx.x];
    }
    if (threadIdx.x < DH * DH) s_wdot[threadIdx.x] = wdot[threadIdx.x];
    __syncthreads();

    int warp = threadIdx.x >> 5;
    int lane = threadIdx.x & 31;
    int widx = blockIdx.x * (blockDim.x >> 5) + warp;
    if (widx >= e_count) return;
    int e = g_eorder[widx];

    int src = ei[e];
    int dst = ei[e_count + e];
    float shv = esh[e];

    // radial MLP layer 1 + SiLU (lane owns hidden units lane, lane+32)
    float rv = (lane < NB) ? remb[(size_t)e * NB + lane] : 0.f;
    float zk0 = s_b1k[lane], zk1 = s_b1k[lane + 32];
    float zv0 = s_b1v[lane], zv1 = s_b1v[lane + 32];
#pragma unroll
    for (int r = 0; r < NB; r++) {
        float x = __shfl_sync(0xffffffffu, rv, r);
        zk0 = fmaf(x, s_w1k[r * HID + lane], zk0);
        zk1 = fmaf(x, s_w1k[r * HID + lane + 32], zk1);
        zv0 = fmaf(x, s_w1v[r * HID + lane], zv0);
        zv1 = fmaf(x, s_w1v[r * HID + lane + 32], zv1);
    }
    s_h[warp][lane]      = zk0 / (1.f + expf(-zk0));
    s_h[warp][lane + 32] = zk1 / (1.f + expf(-zk1));
    s_h[warp][lane + 64] = zv0 / (1.f + expf(-zv0));
    s_h[warp][lane + 96] = zv1 / (1.f + expf(-zv1));
    __syncwarp();

    // contract hidden with fp16 P rows (coalesced: lane stride 16B per load)
    const uint4* pk4 = (const uint4*)(g_Pk16 + (size_t)src * 2048 + lane * 8);
    const uint4* pv4 = (const uint4*)(g_Pv16 + (size_t)src * 2048 + lane * 8);
    float ak = g_Pbk[src * 32 + lane];
    float av = g_Pbv[src * 32 + lane];
#pragma unroll
    for (int hb = 0; hb < 8; hb++) {
        uint4 vk = pk4[hb * 32];         // 32 uint4 per hb block (k-stride)
        uint4 vv = pv4[hb * 32];
        const __half2* hk = (const __half2*)&vk;
        const __half2* hv = (const __half2*)&vv;
#pragma unroll
        for (int u = 0; u < 4; u++) {
            float2 hidk = *(const float2*)&s_h[warp][hb * 8 + 2 * u];
            float2 hidv = *(const float2*)&s_h[warp][64 + hb * 8 + 2 * u];
            float2 pk = __half22float2(hk[u]);
            float2 pv = __half22float2(hv[u]);
            ak = fmaf(hidk.x, pk.x, ak);
            ak = fmaf(hidk.y, pk.y, ak);
            av = fmaf(hidv.x, pv.x, av);
            av = fmaf(hidv.y, pv.y, av);
        }
    }
    float k_e = shv * ak;
    float v_e = shv * av;

    // per-head bilinear logit
    int head = lane >> 3;
    int j = lane & 7;
    float qv = g_q[dst * 32 + lane];
    float cj = 0.f;
#pragma unroll
    for (int i = 0; i < DH; i++) {
        float qi = __shfl_sync(0xffffffffu, qv, head * 8 + i);
        cj = fmaf(qi, s_wdot[i * 8 + j], cj);
    }
    float prod = cj * k_e;
    prod += __shfl_xor_sync(0xffffffffu, prod, 1);
    prod += __shfl_xor_sync(0xffffffffu, prod, 2);
    prod += __shfl_xor_sync(0xffffffffu, prod, 4);

    float max_r = decode_scalar(maxr_p);
    float L = elen[e];
    float cut = 1.f / (1.f + expf(-10.f * (1.f - L / max_r)));
    float logit = prod * DOT_SCALE * cut;
    float ex = expf(logit);      // |logit| << 1 by construction; no max-shift

    if (j == 0) atomicAdd(&g_den[dst * NHEAD + head], ex);
    atomicAdd(&g_num[dst * 32 + lane], ex * v_e);
}

// ---------------------------------------------------------------------------
// K5: per-node epilogue
// ---------------------------------------------------------------------------
__global__ void k5_final(const float* __restrict__ nf,
                         const float* __restrict__ w_out,
                         const float* __restrict__ ffn_w1,
                         const float* __restrict__ ffn_w2,
                         float* __restrict__ out, int n) {
    __shared__ float s_wo[1024], s_f1[2048], s_f2[2048];
    for (int i = threadIdx.x; i < 1024; i += blockDim.x) s_wo[i] = w_out[i];
    for (int i = threadIdx.x; i < 2048; i += blockDim.x) {
        s_f1[i] = ffn_w1[i];
        s_f2[i] = ffn_w2[i];
    }
    __syncthreads();
    int warp = threadIdx.x >> 5;
    int lane = threadIdx.x & 31;
    int node = blockIdx.x * (blockDim.x >> 5) + warp;
    if (node >= n) return;

    float numv = g_num[node * 32 + lane];
    float den = g_den[node * NHEAD + (lane >> 3)];
    float agg = (den > 0.f) ? numv / den : 0.f;

    float o = 0.f;
#pragma unroll
    for (int i = 0; i < 32; i++) {
        float a = __shfl_sync(0xffffffffu, agg, i);
        o = fmaf(a, s_wo[i * 32 + lane], o);
    }
    float attn = nf[node * 32 + lane] + o * INV_SQRT_C;

    float h0 = 0.f, h1 = 0.f;
#pragma unroll
    for (int i = 0; i < 32; i++) {
        float a = __shfl_sync(0xffffffffu, attn, i);
        h0 = fmaf(a, s_f1[i * 64 + lane], h0);
        h1 = fmaf(a, s_f1[i * 64 + lane + 32], h1);
    }
    h0 *= INV_SQRT_C;
    h1 *= INV_SQRT_C;
    float g0 = h0 / (1.f + expf(-fabsf(h0)));
    float g1 = h1 / (1.f + expf(-fabsf(h1)));

    float f = 0.f;
#pragma unroll
    for (int jj = 0; jj < 64; jj++) {
        float g = __shfl_sync(0xffffffffu, (jj < 32) ? g0 : g1, jj & 31);
        f = fmaf(g, s_f2[jj * 32 + lane], f);
    }
    out[node * 32 + lane] = attn + f * 0.125f;
}

// ---------------------------------------------------------------------------
extern "C" void kernel_launch(void* const* d_in, const int* in_sizes, int n_in,
                              void* d_out, int out_size) {
    const float* nf     = (const float*)d_in[0];
    const int*   ei     = (const int*)d_in[1];
    const float* esh    = (const float*)d_in[2];
    const float* remb   = (const float*)d_in[3];
    const float* elen   = (const float*)d_in[4];
    const int*   maxr   = (const int*)d_in[5];
    const float* w_q    = (const float*)d_in[6];
    const float* fck_w1 = (const float*)d_in[7];
    const float* fck_b1 = (const float*)d_in[8];
    const float* fck_w2 = (const float*)d_in[9];
    const float* fck_b2 = (const float*)d_in[10];
    const float* fcv_w1 = (const float*)d_in[11];
    const float* fcv_b1 = (const float*)d_in[12];
    const float* fcv_w2 = (const float*)d_in[13];
    const float* fcv_b2 = (const float*)d_in[14];
    const float* w_dot  = (const float*)d_in[15];
    const float* w_out  = (const float*)d_in[16];
    const float* ffn_w1 = (const float*)d_in[17];
    const float* ffn_w2 = (const float*)d_in[18];

    int n = in_sizes[0] / CC;
    int e = in_sizes[1] / 2;

    int tot0 = n * (CC + NHEAD + 1);
    k0_init<<<(tot0 + 255) / 256, 256>>>(n);
    kt_transpose<<<(2 * 65536 + 255) / 256, 256>>>(fck_w2, fcv_w2);
    kh_hist<<<(e + 255) / 256, 256>>>(ei, e);
    ksA_blocksum<<<SCAN_BLK, 1024>>>(n);
    ksB_scanblk<<<1, 32>>>();
    ksC_scan<<<SCAN_BLK, 1024>>>(n);
    kc_scatter<<<(e + 255) / 256, 256>>>(ei, e);
    k1_node_pre<<<(n + 7) / 8, 256>>>(nf, w_q, fck_b2, fcv_b2, n);
    dim3 g2((n + 127) / 128, 16, 2);
    k2_pgemm<<<g2, 256>>>(nf, n);
    k3_edge<<<(e + 7) / 8, 256>>>(ei, esh, remb, elen, fck_w1, fck_b1,
                                  fcv_w1, fcv_b1, w_dot, maxr, e);
    k5_final<<<(n + 7) / 8, 256>>>(nf, w_out, ffn_w1, ffn_w2, (float*)d_out, n);
}